// round 2
// baseline (speedup 1.0000x reference)
#include <cuda_runtime.h>
#include <cuda_bf16.h>
#include <cstdint>

#define NU 100000
#define NI 100000
#define D  128

typedef unsigned long long ull;

// ---------------- scratch (static device globals; no allocation) ----------------
__device__ __align__(16) float g_agg_ui[(size_t)NI * D];  // sum feat_user over ui edges -> item
__device__ __align__(16) float g_agg_iu[(size_t)NU * D];  // sum feat_item over iu edges -> user
__device__ __align__(16) float g_agg_uu[(size_t)NU * D];  // sum feat_user over uu edges -> user
__device__ float g_deg_ui[NI];
__device__ float g_deg_iu[NU];
__device__ float g_deg_uu[NU];

// ---------------- packed f32x2 helpers (sm_100+/sm_103a) ----------------
__device__ __forceinline__ void fma2(ull& d, ull a, ull b) {
    asm("fma.rn.f32x2 %0, %1, %2, %0;" : "+l"(d) : "l"(a), "l"(b));
}
__device__ __forceinline__ ull splat2(float x) {
    ull r; asm("mov.b64 %0, {%1, %1};" : "=l"(r) : "f"(x)); return r;
}
__device__ __forceinline__ float2 unpack2(ull v) {
    float lo, hi; asm("mov.b64 {%0, %1}, %2;" : "=f"(lo), "=f"(hi) : "l"(v));
    return make_float2(lo, hi);
}

// ---------------- zero scratch ----------------
__global__ void zero_kernel() {
    size_t i = (size_t)blockIdx.x * blockDim.x + threadIdx.x;
    size_t stride = (size_t)gridDim.x * blockDim.x;
    const size_t n4 = (size_t)NI * D / 4;  // NU == NI
    float4 z = make_float4(0.f, 0.f, 0.f, 0.f);
    for (size_t j = i; j < n4; j += stride) {
        reinterpret_cast<float4*>(g_agg_ui)[j] = z;
        reinterpret_cast<float4*>(g_agg_iu)[j] = z;
        reinterpret_cast<float4*>(g_agg_uu)[j] = z;
    }
    for (size_t j = i; j < (size_t)NI; j += stride) {
        g_deg_ui[j] = 0.f;
        g_deg_iu[j] = 0.f;
        g_deg_uu[j] = 0.f;
    }
}

// ---------------- edge aggregation: one warp per edge ----------------
// which: 0 = ui (into item), 1 = iu (into user), 2 = uu (into user)
__global__ __launch_bounds__(256) void edge_agg_kernel(
    const float* __restrict__ feat,
    const int* __restrict__ src,
    const int* __restrict__ dst,
    int E, int which)
{
    float* agg = (which == 0) ? g_agg_ui : (which == 1) ? g_agg_iu : g_agg_uu;
    float* deg = (which == 0) ? g_deg_ui : (which == 1) ? g_deg_iu : g_deg_uu;

    int w    = (int)(((size_t)blockIdx.x * blockDim.x + threadIdx.x) >> 5);
    int lane = threadIdx.x & 31;
    if (w >= E) return;

    int s = src[w];
    int d = dst[w];

    // 32 lanes x float4 = full 512B row gather, coalesced
    float4 v = reinterpret_cast<const float4*>(feat + (size_t)s * D)[lane];
    // vector RED (sm_90+): 512B contiguous atomic scatter per warp
    atomicAdd(reinterpret_cast<float4*>(agg + (size_t)d * D) + lane, v);
    if (lane == 0) atomicAdd(deg + d, 1.0f);
}

// ---------------- fused GEMM ----------------
// mode 0 (item):  out = mask_ui .* ((agg_ui/deg_ui) @ W0 + b0)
// mode 1 (user):  out = mask_iu .* ((agg_iu/deg_iu) @ W0 + b0)
//                     + mask_uu .* ((agg_uu/deg_uu) @ W1 + b1)   [single pass, reg-accumulated]
// Block tile 64x128, K chunked by 16, 256 threads, 8x4 micro-tile via f32x2 row-pairs.
#define ASTRIDE 66   // padded k-major A tile row stride (conflict-free stores, 8B-aligned pair loads)

__global__ __launch_bounds__(256) void gemm_fused_kernel(
    const float* __restrict__ W0, const float* __restrict__ b0,
    const float* __restrict__ W1, const float* __restrict__ b1,
    float* __restrict__ out, int M, int mode)
{
    __shared__ float W_s[16 * D];          // 8 KB  : current K-chunk of W (k-major rows)
    __shared__ float A_s[16 * ASTRIDE];    // 4.1 KB: current K-chunk of A tile, k-major, pre-scaled
    __shared__ float s2_s[2][64];          // per-row 1/deg per etype (0 if isolated)
    __shared__ float b2_s[2][D];

    const int t  = threadIdx.x;
    const int tx = t & 31;   // col group (4 cols each)
    const int ty = t >> 5;   // row group (8 rows each)
    const int m0 = blockIdx.x * 64;

    const int net = (mode == 0) ? 1 : 2;
    const float* Asel[2];
    const float* dsel[2];
    if (mode == 0) { Asel[0] = g_agg_ui; dsel[0] = g_deg_ui; Asel[1] = g_agg_ui; dsel[1] = g_deg_ui; }
    else           { Asel[0] = g_agg_iu; dsel[0] = g_deg_iu; Asel[1] = g_agg_uu; dsel[1] = g_deg_uu; }

    // stage per-row scales and biases
    if (t < 128) {
        int e = t >> 6, r = t & 63;
        if (e < net) {
            int row = m0 + r;
            float dg = (row < M) ? dsel[e][row] : 0.f;
            s2_s[e][r] = (dg > 0.f) ? (1.f / dg) : 0.f;
        } else {
            s2_s[e][r] = 0.f;
        }
    }
    if (t < D) b2_s[0][t] = b0[t];
    else if (t < 2 * D) b2_s[1][t - D] = (net == 2) ? b1[t - D] : 0.f;

    // acc2[p][c] packs output rows (ty*8+2p, ty*8+2p+1) for col tx*4+c
    ull acc2[4][4];
#pragma unroll
    for (int p = 0; p < 4; ++p)
#pragma unroll
        for (int c = 0; c < 4; ++c) acc2[p][c] = 0ull;

    // A staging mapping: thread t handles row ar = t>>2, k offsets ac..ac+3 within chunk
    const int ar = t >> 2;
    const int ac = (t & 3) * 4;
    const int arow = m0 + ar;

    for (int e = 0; e < net; ++e) {
        const float* A = Asel[e];
        const float* W = (e == 0) ? W0 : W1;
#pragma unroll 1
        for (int kc = 0; kc < 8; ++kc) {
            __syncthreads();
            // stage W chunk: 16x128 floats = 512 float4, 2 per thread
            {
                const float4* Wg = reinterpret_cast<const float4*>(W + (size_t)kc * 16 * D);
                reinterpret_cast<float4*>(W_s)[t]       = Wg[t];
                reinterpret_cast<float4*>(W_s)[t + 256] = Wg[t + 256];
            }
            // stage A chunk (transposed to k-major) with 1/deg folded in
            {
                float4 v = make_float4(0.f, 0.f, 0.f, 0.f);
                if (arow < M)
                    v = *reinterpret_cast<const float4*>(A + (size_t)arow * D + kc * 16 + ac);
                float sc = s2_s[e][ar];
                A_s[(ac + 0) * ASTRIDE + ar] = v.x * sc;
                A_s[(ac + 1) * ASTRIDE + ar] = v.y * sc;
                A_s[(ac + 2) * ASTRIDE + ar] = v.z * sc;
                A_s[(ac + 3) * ASTRIDE + ar] = v.w * sc;
            }
            __syncthreads();

#pragma unroll
            for (int k = 0; k < 16; ++k) {
                const float* As = &A_s[k * ASTRIDE + ty * 8];
                ull a0 = *reinterpret_cast<const ull*>(As + 0);
                ull a1 = *reinterpret_cast<const ull*>(As + 2);
                ull a2 = *reinterpret_cast<const ull*>(As + 4);
                ull a3 = *reinterpret_cast<const ull*>(As + 6);
                float4 w = reinterpret_cast<const float4*>(W_s + k * D)[tx];
                ull w0 = splat2(w.x), w1 = splat2(w.y), w2 = splat2(w.z), w3 = splat2(w.w);
                fma2(acc2[0][0], a0, w0); fma2(acc2[0][1], a0, w1);
                fma2(acc2[0][2], a0, w2); fma2(acc2[0][3], a0, w3);
                fma2(acc2[1][0], a1, w0); fma2(acc2[1][1], a1, w1);
                fma2(acc2[1][2], a1, w2); fma2(acc2[1][3], a1, w3);
                fma2(acc2[2][0], a2, w0); fma2(acc2[2][1], a2, w1);
                fma2(acc2[2][2], a2, w2); fma2(acc2[2][3], a2, w3);
                fma2(acc2[3][0], a3, w0); fma2(acc2[3][1], a3, w1);
                fma2(acc2[3][2], a3, w2); fma2(acc2[3][3], a3, w3);
            }
        }
    }

    // epilogue: unpack row-pairs, add masked biases, store
#pragma unroll
    for (int p = 0; p < 4; ++p) {
        int lr0 = ty * 8 + 2 * p;
        int row0 = m0 + lr0;
        float mask0_lo = (s2_s[0][lr0]     > 0.f) ? 1.f : 0.f;
        float mask0_hi = (s2_s[0][lr0 + 1] > 0.f) ? 1.f : 0.f;
        float mask1_lo = (s2_s[1][lr0]     > 0.f) ? 1.f : 0.f;
        float mask1_hi = (s2_s[1][lr0 + 1] > 0.f) ? 1.f : 0.f;

        float2 v0 = unpack2(acc2[p][0]);
        float2 v1 = unpack2(acc2[p][1]);
        float2 v2 = unpack2(acc2[p][2]);
        float2 v3 = unpack2(acc2[p][3]);

        const float* bb0 = &b2_s[0][tx * 4];
        const float* bb1 = &b2_s[1][tx * 4];

        if (row0 < M) {
            float4 o;
            o.x = v0.x + mask0_lo * bb0[0] + mask1_lo * bb1[0];
            o.y = v1.x + mask0_lo * bb0[1] + mask1_lo * bb1[1];
            o.z = v2.x + mask0_lo * bb0[2] + mask1_lo * bb1[2];
            o.w = v3.x + mask0_lo * bb0[3] + mask1_lo * bb1[3];
            reinterpret_cast<float4*>(out + (size_t)row0 * D)[tx] = o;
        }
        if (row0 + 1 < M) {
            float4 o;
            o.x = v0.y + mask0_hi * bb0[0] + mask1_hi * bb1[0];
            o.y = v1.y + mask0_hi * bb0[1] + mask1_hi * bb1[1];
            o.z = v2.y + mask0_hi * bb0[2] + mask1_hi * bb1[2];
            o.w = v3.y + mask0_hi * bb0[3] + mask1_hi * bb1[3];
            reinterpret_cast<float4*>(out + (size_t)(row0 + 1) * D)[tx] = o;
        }
    }
}

extern "C" void kernel_launch(void* const* d_in, const int* in_sizes, int n_in,
                              void* d_out, int out_size)
{
    const float* feat_user = (const float*)d_in[0];
    const float* feat_item = (const float*)d_in[1];
    const float* W_ui = (const float*)d_in[2];
    const float* b_ui = (const float*)d_in[3];
    const float* W_iu = (const float*)d_in[4];
    const float* b_iu = (const float*)d_in[5];
    const float* W_uu = (const float*)d_in[6];
    const float* b_uu = (const float*)d_in[7];
    const int* src_ui = (const int*)d_in[8];
    const int* dst_ui = (const int*)d_in[9];
    const int* src_iu = (const int*)d_in[10];
    const int* dst_iu = (const int*)d_in[11];
    const int* src_uu = (const int*)d_in[12];
    const int* dst_uu = (const int*)d_in[13];

    const int E_ui = in_sizes[8];
    const int E_iu = in_sizes[10];
    const int E_uu = in_sizes[12];

    float* out      = (float*)d_out;
    float* out_user = out;                      // slot 0 of [2, NU, 128]
    float* out_item = out + (size_t)NU * D;     // slot 1

    (void)n_in; (void)out_size;

    // 1) zero scratch accumulators + degrees
    zero_kernel<<<1024, 256>>>();

    // 2) edge aggregations on raw features (projection commutes with mean)
    edge_agg_kernel<<<(E_ui + 7) / 8, 256>>>(feat_user, src_ui, dst_ui, E_ui, 0);
    edge_agg_kernel<<<(E_iu + 7) / 8, 256>>>(feat_item, src_iu, dst_iu, E_iu, 1);
    edge_agg_kernel<<<(E_uu + 7) / 8, 256>>>(feat_user, src_uu, dst_uu, E_uu, 2);

    // 3) fused projection + mean-normalize + mask + bias (user = iu + uu in one pass)
    const int GB_I = (NI + 63) / 64;
    const int GB_U = (NU + 63) / 64;
    gemm_fused_kernel<<<GB_I, 256>>>(W_ui, b_ui, W_ui, b_ui, out_item, NI, /*mode=*/0);
    gemm_fused_kernel<<<GB_U, 256>>>(W_iu, b_iu, W_uu, b_uu, out_user, NU, /*mode=*/1);
}